// round 8
// baseline (speedup 1.0000x reference)
#include <cuda_runtime.h>
#include <cuda_fp16.h>
#include <cstdint>
#include <cstddef>

// ================= problem constants =================
#define NB 8
#define NC 32
#define C4 128
#define H1 112
#define H2 56
#define H3 28
#define M1 (NB * H1 * H1)     // 100352
#define M2 (NB * H2 * H2)     // 25088
#define M3 (NB * H3 * H3)     // 6272

#define BM 128
#define NCHUNK 18              // 9 taps x 2 k-halves (BK=64)
#define A_BYTES 16384          // 128 rows x 128B
#define B_BYTES 16384
#define STAGE_BYTES (A_BYTES + B_BYTES)
#define NPIPE 3
#define SMEM_TOTAL (NPIPE * STAGE_BYTES)   // 98304 -> 2 CTAs/SM

#define NB1 (M1 / BM)          // 784
#define NB2 (M2 / BM)          // 196
#define NB3 (M3 / BM)          // 49
#define WCONV_BLKS ((9 * C4 * C4) / 256)   // 576

// ================= scratch =================
__device__ __half g_a1[(size_t)M1 * C4];
__device__ __half g_a2[(size_t)M2 * C4];
__device__ __half g_a3[(size_t)M3 * C4];
__device__ float g_ll1[(size_t)M1 * NC];
__device__ float g_ll2[(size_t)M2 * NC];
__device__ float g_y1 [(size_t)M1 * C4];
__device__ float g_y2 [(size_t)M2 * C4];
__device__ float g_y3 [(size_t)M3 * C4];
__device__ float g_r2 [(size_t)M2 * NC];
__device__ float g_r1 [(size_t)M1 * NC];
__device__ __half g_w[(size_t)9 * C4 * C4];    // [tap][n][ic]

// ================= helpers =================
__device__ __forceinline__ uint32_t smem_u32(const void* p) {
    uint32_t a;
    asm("{ .reg .u64 t; cvta.to.shared.u64 t, %1; cvt.u32.u64 %0, t; }" : "=r"(a) : "l"(p));
    return a;
}
__device__ __forceinline__ void ldsm_x4(uint32_t& r0, uint32_t& r1, uint32_t& r2, uint32_t& r3,
                                        uint32_t addr) {
    asm volatile("ldmatrix.sync.aligned.m8n8.x4.shared.b16 {%0,%1,%2,%3}, [%4];"
                 : "=r"(r0), "=r"(r1), "=r"(r2), "=r"(r3) : "r"(addr));
}
__device__ __forceinline__ void mma16816(float* c, const uint32_t* a, const uint32_t* b) {
    asm volatile(
        "mma.sync.aligned.m16n8k16.row.col.f32.f16.f16.f32 "
        "{%0,%1,%2,%3}, {%4,%5,%6,%7}, {%8,%9}, {%0,%1,%2,%3};"
        : "+f"(c[0]), "+f"(c[1]), "+f"(c[2]), "+f"(c[3])
        : "r"(a[0]), "r"(a[1]), "r"(a[2]), "r"(a[3]), "r"(b[0]), "r"(b[1]));
}
__device__ __forceinline__ void cp16(uint32_t saddr, const void* gptr, uint32_t srcsz) {
    size_t ga = __cvta_generic_to_global(gptr);
    asm volatile("cp.async.ca.shared.global [%0], [%1], 16, %2;"
                 :: "r"(saddr), "l"(ga), "r"(srcsz) : "memory");
}
#define CP_COMMIT() asm volatile("cp.async.commit_group;" ::: "memory")
#define CP_WAIT1()  asm volatile("cp.async.wait_group 1;" ::: "memory")

// ================= DWT level1 + fused weight convert =================
__global__ void dwt1w_k(const float* __restrict__ x, __half* __restrict__ oh16,
                        float* __restrict__ oLL, const float* __restrict__ w,
                        __half* __restrict__ wh) {
    if (blockIdx.x < WCONV_BLKS) {
        int idx = blockIdx.x * 256 + threadIdx.x;
        int tap = idx / (C4 * C4);
        int rem = idx - tap * C4 * C4;
        int o = rem >> 7, ic = rem & 127;
        wh[idx] = __float2half(w[((size_t)o * C4 + ic) * 9 + tap]);
        return;
    }
    long idx = (long)(blockIdx.x - WCONV_BLKS) * 256 + threadIdx.x;
    long total = (long)M1 * NC;
    if (idx >= total) return;
    const int h = H1, wd = H1, wIn = 224;
    int c = (int)(idx & 31);
    long t = idx >> 5;
    int j = (int)(t % wd); t /= wd;
    int i = (int)(t % h);
    int b = (int)(t / h);

    const float* s = x + (((size_t)(b * NC + c)) * (2 * h) + 2 * i) * (size_t)wIn + 2 * j;
    float a = s[0], bb = s[1], cc = s[wIn], dd = s[wIn + 1];
    float ll = (a + bb + cc + dd) * 0.5f;
    float lh = (a - bb + cc - dd) * 0.5f;
    float hl = (a + bb - cc - dd) * 0.5f;
    float hh = (a - bb - cc + dd) * 0.5f;

    size_t pos = (size_t)(b * h + i) * wd + j;
    __half2 p0 = __floats2half2_rn(ll, lh);
    __half2 p1 = __floats2half2_rn(hl, hh);
    uint2 v; v.x = *(uint32_t*)&p0; v.y = *(uint32_t*)&p1;
    *(uint2*)(oh16 + pos * C4 + c * 4) = v;
    oLL[pos * NC + c] = ll;
}

// NHWC-32 input DWT (levels 2,3)
__global__ void dwt_k(const float* __restrict__ src, int wIn,
                      __half* __restrict__ oh16, float* __restrict__ oLL, int h, int w) {
    long total = (long)NB * h * w * NC;
    long idx = (long)blockIdx.x * 256 + threadIdx.x;
    if (idx >= total) return;
    int c = (int)(idx & 31);
    long t = idx >> 5;
    int j = (int)(t % w); t /= w;
    int i = (int)(t % h);
    int b = (int)(t / h);

    const float* s = src + (((size_t)b * (2 * h) + 2 * i) * (size_t)wIn + 2 * j) * NC + c;
    float a = s[0], bb = s[NC], cc = s[(size_t)wIn * NC], dd = s[(size_t)wIn * NC + NC];
    float ll = (a + bb + cc + dd) * 0.5f;
    float lh = (a - bb + cc - dd) * 0.5f;
    float hl = (a + bb - cc - dd) * 0.5f;
    float hh = (a - bb - cc + dd) * 0.5f;

    size_t pos = (size_t)(b * h + i) * w + j;
    __half2 p0 = __floats2half2_rn(ll, lh);
    __half2 p1 = __floats2half2_rn(hl, hh);
    uint2 v; v.x = *(uint32_t*)&p0; v.y = *(uint32_t*)&p1;
    *(uint2*)(oh16 + pos * C4 + c * 4) = v;
    if (oLL) oLL[pos * NC + c] = ll;
}

// ================= IDWT =================
__global__ void idwt_k(const float* __restrict__ y, const float* __restrict__ addll,
                       float* __restrict__ out, int h, int w, int finalOut,
                       const float* __restrict__ bias) {
    long total = (long)NB * h * w * NC;
    long idx = (long)blockIdx.x * 256 + threadIdx.x;
    if (idx >= total) return;
    int c = (int)(idx & 31);
    long t = idx >> 5;
    int j = (int)(t % w); t /= w;
    int i = (int)(t % h);
    int b = (int)(t / h);

    size_t pos = (size_t)(b * h + i) * w + j;
    float4 s = *(const float4*)(y + pos * C4 + c * 4);
    float ll = s.x, lh = s.y, hl = s.z, hh = s.w;
    if (addll) ll += addll[pos * NC + c];
    float a  = (ll + lh + hl + hh) * 0.5f;
    float bb = (ll - lh + hl - hh) * 0.5f;
    float cc = (ll + lh - hl - hh) * 0.5f;
    float dd = (ll - lh - hl + hh) * 0.5f;

    int H = 2 * h, W = 2 * w;
    if (finalOut) {
        float bv = bias[c];
        float* o = out + (((size_t)(b * NC + c)) * H + 2 * i) * (size_t)W + 2 * j;
        o[0] = a + bv; o[1] = bb + bv;
        o[W] = cc + bv; o[W + 1] = dd + bv;
    } else {
        float* o = out + (((size_t)b * H + 2 * i) * (size_t)W + 2 * j) * NC + c;
        o[0] = a; o[NC] = bb;
        o[(size_t)W * NC] = cc; o[(size_t)W * NC + NC] = dd;
    }
}

// ================= conv: all 3 levels, 128 threads, 4 warps of 64x64 =================
__global__ __launch_bounds__(128, 2)
void conv_mma(const __half* __restrict__ a1, float* __restrict__ y1,
              const __half* __restrict__ a2, float* __restrict__ y2,
              const __half* __restrict__ a3, float* __restrict__ y3,
              const __half* __restrict__ wgt) {
    extern __shared__ __align__(128) char smem[];
    const uint32_t sb = smem_u32(smem);

    const __half* act; float* y; int h, bx;
    if ((int)blockIdx.x < NB1)            { act = a1; y = y1; h = H1; bx = blockIdx.x; }
    else if ((int)blockIdx.x < NB1 + NB2) { act = a2; y = y2; h = H2; bx = blockIdx.x - NB1; }
    else                                  { act = a3; y = y3; h = H3; bx = blockIdx.x - NB1 - NB2; }
    const int w = h;
    const int hw = h * w;
    const int m0 = bx * BM;

    const int tid = threadIdx.x;
    const int lane = tid & 31;
    const int wid = tid >> 5;
    const int wm = wid & 1;        // 2 warps along M (64 rows)
    const int wn = wid >> 1;       // 2 warps along N (64 cols)

    // ---- A loader: row = tid (0..127) ----
    const int mg = m0 + tid;
    const int b   = mg / hw;
    const int pos = mg - b * hw;
    const int oh = pos / w;
    const int ow = pos - oh * w;
    const size_t aBase = (size_t)b * hw * C4;
    const uint32_t stRow = (uint32_t)tid * 128;
    const int rx = tid & 7;

    // ---- ldmatrix geometry ----
    uint32_t aRowOff[4]; int aSx[4];
#pragma unroll
    for (int mt = 0; mt < 4; mt++) {
        int rowA = wm * 64 + mt * 16 + (lane & 15);
        aRowOff[mt] = (uint32_t)rowA * 128;
        aSx[mt] = rowA & 7;
    }
    const int aSegBase = lane >> 4;
    uint32_t bRowOff[4]; int bSx[4];
#pragma unroll
    for (int bt = 0; bt < 4; bt++) {
        int rowB = wn * 64 + bt * 16 + (lane & 7) + ((lane & 16) >> 1);
        bRowOff[bt] = (uint32_t)rowB * 128;
        bSx[bt] = rowB & 7;
    }
    const int bSegBase = (lane >> 3) & 1;

    float acc[4][8][4];
#pragma unroll
    for (int i = 0; i < 4; i++)
#pragma unroll
        for (int j = 0; j < 8; j++)
#pragma unroll
            for (int q = 0; q < 4; q++) acc[i][j][q] = 0.0f;

    auto load_chunk = [&](int ch, uint32_t st) {
        const int tap = ch >> 1;
        const int kc  = ch & 1;
        const int kh = tap / 3 - 1;
        const int kw = tap - (tap / 3) * 3 - 1;
        // A: one row (tid), 8 x 16B
        {
            int ih = oh + kh, iw = ow + kw;
            bool v = ((unsigned)ih < (unsigned)h) && ((unsigned)iw < (unsigned)w);
            uint32_t sz = v ? 16u : 0u;
            const char* pa = (const char*)(act + aBase + ((size_t)ih * w + iw) * C4 + kc * 64);
#pragma unroll
            for (int s = 0; s < 8; s++)
                cp16(st + stRow + (uint32_t)(s ^ rx) * 16, pa + s * 16, sz);
        }
        // B: one n-row (tid), 8 x 16B
        {
            const char* pb = (const char*)(wgt + ((size_t)tap * C4 + tid) * C4 + kc * 64);
#pragma unroll
            for (int s = 0; s < 8; s++)
                cp16(st + A_BYTES + stRow + (uint32_t)(s ^ rx) * 16, pb + s * 16, 16u);
        }
    };

    load_chunk(0, sb);
    CP_COMMIT();
    load_chunk(1, sb + STAGE_BYTES);
    CP_COMMIT();

    uint32_t stC = sb;
    uint32_t stL = sb + 2u * STAGE_BYTES;
    const uint32_t stEnd = sb + 3u * STAGE_BYTES;

#pragma unroll 1
    for (int ch = 0; ch < NCHUNK; ch++) {
        CP_WAIT1();
        __syncthreads();
        if (ch + 2 < NCHUNK) load_chunk(ch + 2, stL);
        CP_COMMIT();

        const uint32_t bufA = stC;
        const uint32_t bufB = stC + A_BYTES;
#pragma unroll
        for (int ks = 0; ks < 4; ks++) {
            uint32_t af[4][4];
#pragma unroll
            for (int mt = 0; mt < 4; mt++)
                ldsm_x4(af[mt][0], af[mt][1], af[mt][2], af[mt][3],
                        bufA + aRowOff[mt] + (uint32_t)((ks * 2 + aSegBase) ^ aSx[mt]) * 16);
            uint32_t bf[8][2];
#pragma unroll
            for (int bt = 0; bt < 4; bt++) {
                uint32_t r0, r1, r2, r3;
                ldsm_x4(r0, r1, r2, r3,
                        bufB + bRowOff[bt] + (uint32_t)((ks * 2 + bSegBase) ^ bSx[bt]) * 16);
                bf[bt * 2 + 0][0] = r0; bf[bt * 2 + 0][1] = r1;
                bf[bt * 2 + 1][0] = r2; bf[bt * 2 + 1][1] = r3;
            }
#pragma unroll
            for (int mt = 0; mt < 4; mt++)
#pragma unroll
                for (int nt = 0; nt < 8; nt++)
                    mma16816(acc[mt][nt], af[mt], bf[nt]);
        }

        stC += STAGE_BYTES; if (stC >= stEnd) stC = sb;
        stL += STAGE_BYTES; if (stL >= stEnd) stL = sb;
    }

    // ---- epilogue ----
    const int mBase = m0 + wm * 64 + (lane >> 2);
    const int nBase = wn * 64 + (lane & 3) * 2;
#pragma unroll
    for (int mt = 0; mt < 4; mt++) {
        int m = mBase + mt * 16;
        float* d0 = y + (size_t)m * C4 + nBase;
        float* d1 = d0 + 8 * C4;
#pragma unroll
        for (int nt = 0; nt < 8; nt++) {
            *(float2*)(d0 + nt * 8) = make_float2(acc[mt][nt][0], acc[mt][nt][1]);
            *(float2*)(d1 + nt * 8) = make_float2(acc[mt][nt][2], acc[mt][nt][3]);
        }
    }
}

// ================= launch =================
static inline int cdiv(long a, int b) { return (int)((a + b - 1) / b); }

extern "C" void kernel_launch(void* const* d_in, const int* in_sizes, int n_in,
                              void* d_out, int out_size) {
    const float* x    = (const float*)d_in[0];
    const float* wgt  = (const float*)d_in[1];
    const float* bias = (const float*)d_in[2];
    float* out = (float*)d_out;

    __half *a1, *a2, *a3, *wh;
    float *ll1, *ll2, *y1, *y2, *y3, *r2, *r1;
    cudaGetSymbolAddress((void**)&a1, g_a1);
    cudaGetSymbolAddress((void**)&a2, g_a2);
    cudaGetSymbolAddress((void**)&a3, g_a3);
    cudaGetSymbolAddress((void**)&wh, g_w);
    cudaGetSymbolAddress((void**)&ll1, g_ll1);  cudaGetSymbolAddress((void**)&ll2, g_ll2);
    cudaGetSymbolAddress((void**)&y1, g_y1);    cudaGetSymbolAddress((void**)&y2, g_y2);
    cudaGetSymbolAddress((void**)&y3, g_y3);
    cudaGetSymbolAddress((void**)&r2, g_r2);    cudaGetSymbolAddress((void**)&r1, g_r1);

    cudaFuncSetAttribute(conv_mma, cudaFuncAttributeMaxDynamicSharedMemorySize, SMEM_TOTAL);

    // 0: dwt level1 + fused weight convert
    dwt1w_k<<<WCONV_BLKS + cdiv((long)M1 * NC, 256), 256>>>(x, a1, ll1, wgt, wh);
    // 1: dwt level2
    dwt_k<<<cdiv((long)M2 * NC, 256), 256>>>(ll1, H1, a2, ll2, H2, H2);
    // 2: dwt level3
    dwt_k<<<cdiv((long)M3 * NC, 256), 256>>>(ll2, H2, a3, nullptr, H3, H3);
    // 3: all convs (profiled index)
    conv_mma<<<NB1 + NB2 + NB3, 128, SMEM_TOTAL>>>(a1, y1, a2, y2, a3, y3, wh);
    // 4-6: reconstruction
    idwt_k<<<cdiv((long)M3 * NC, 256), 256>>>(y3, nullptr, r2, H3, H3, 0, nullptr);
    idwt_k<<<cdiv((long)M2 * NC, 256), 256>>>(y2, r2, r1, H2, H2, 0, nullptr);
    idwt_k<<<cdiv((long)M1 * NC, 256), 256>>>(y1, r1, out, H1, H1, 1, bias);
}

// round 9
// speedup vs baseline: 1.3070x; 1.3070x over previous
#include <cuda_runtime.h>
#include <cuda_fp16.h>
#include <cstdint>
#include <cstddef>

// ================= problem constants =================
#define NB 8
#define NC 32
#define C4 128
#define H1 112
#define H2 56
#define H3 28
#define M1 (NB * H1 * H1)
#define M2 (NB * H2 * H2)
#define M3 (NB * H3 * H3)

// spatial tile: 8 rows (i) x 16 cols (j) = 128 M-rows per block
#define NT1 (NB * 14 * 7)   // 784
#define NT2 (NB * 7 * 4)    // 224
#define NT3 (NB * 4 * 2)    // 64

#define NCHUNK 18           // 9 taps x 2 kc halves (BK=64)
#define HALO_BYTES 46080    // 10*18 cells * 256B
#define B_STAGE 16384       // 128 n-rows x 128B
#define NPIPE 3
#define SMEM_TOTAL (HALO_BYTES + NPIPE * B_STAGE)   // 95232 -> 2 CTAs/SM

#define WCONV_BLKS ((9 * C4 * C4) / 256)   // 576

// ================= scratch =================
__device__ __half g_a1[(size_t)M1 * C4];
__device__ __half g_a2[(size_t)M2 * C4];
__device__ __half g_a3[(size_t)M3 * C4];
__device__ float g_ll1[(size_t)M1 * NC];
__device__ float g_ll2[(size_t)M2 * NC];
__device__ float g_y1 [(size_t)M1 * C4];
__device__ float g_y2 [(size_t)M2 * C4];
__device__ float g_y3 [(size_t)M3 * C4];
__device__ float g_r2 [(size_t)M2 * NC];
__device__ float g_r1 [(size_t)M1 * NC];
__device__ __half g_w[(size_t)9 * C4 * C4];    // [tap][n][ic]

// ================= helpers =================
__device__ __forceinline__ uint32_t smem_u32(const void* p) {
    uint32_t a;
    asm("{ .reg .u64 t; cvta.to.shared.u64 t, %1; cvt.u32.u64 %0, t; }" : "=r"(a) : "l"(p));
    return a;
}
__device__ __forceinline__ void ldsm_x4(uint32_t& r0, uint32_t& r1, uint32_t& r2, uint32_t& r3,
                                        uint32_t addr) {
    asm volatile("ldmatrix.sync.aligned.m8n8.x4.shared.b16 {%0,%1,%2,%3}, [%4];"
                 : "=r"(r0), "=r"(r1), "=r"(r2), "=r"(r3) : "r"(addr));
}
__device__ __forceinline__ void mma16816(float* c, const uint32_t* a, const uint32_t* b) {
    asm volatile(
        "mma.sync.aligned.m16n8k16.row.col.f32.f16.f16.f32 "
        "{%0,%1,%2,%3}, {%4,%5,%6,%7}, {%8,%9}, {%0,%1,%2,%3};"
        : "+f"(c[0]), "+f"(c[1]), "+f"(c[2]), "+f"(c[3])
        : "r"(a[0]), "r"(a[1]), "r"(a[2]), "r"(a[3]), "r"(b[0]), "r"(b[1]));
}
__device__ __forceinline__ void cp16(uint32_t saddr, const void* gptr, uint32_t srcsz) {
    size_t ga = __cvta_generic_to_global(gptr);
    asm volatile("cp.async.ca.shared.global [%0], [%1], 16, %2;"
                 :: "r"(saddr), "l"(ga), "r"(srcsz) : "memory");
}
#define CP_COMMIT() asm volatile("cp.async.commit_group;" ::: "memory")
#define CP_WAIT1()  asm volatile("cp.async.wait_group 1;" ::: "memory")

// ================= DWT level1 + fused weight convert =================
__global__ void dwt1w_k(const float* __restrict__ x, __half* __restrict__ oh16,
                        float* __restrict__ oLL, const float* __restrict__ w,
                        __half* __restrict__ wh) {
    if (blockIdx.x < WCONV_BLKS) {
        int idx = blockIdx.x * 256 + threadIdx.x;
        int tap = idx / (C4 * C4);
        int rem = idx - tap * C4 * C4;
        int o = rem >> 7, ic = rem & 127;
        wh[idx] = __float2half(w[((size_t)o * C4 + ic) * 9 + tap]);
        return;
    }
    long idx = (long)(blockIdx.x - WCONV_BLKS) * 256 + threadIdx.x;
    long total = (long)M1 * NC;
    if (idx >= total) return;
    const int h = H1, wd = H1, wIn = 224;
    int c = (int)(idx & 31);
    long t = idx >> 5;
    int j = (int)(t % wd); t /= wd;
    int i = (int)(t % h);
    int b = (int)(t / h);

    const float* s = x + (((size_t)(b * NC + c)) * (2 * h) + 2 * i) * (size_t)wIn + 2 * j;
    float a = s[0], bb = s[1], cc = s[wIn], dd = s[wIn + 1];
    float ll = (a + bb + cc + dd) * 0.5f;
    float lh = (a - bb + cc - dd) * 0.5f;
    float hl = (a + bb - cc - dd) * 0.5f;
    float hh = (a - bb - cc + dd) * 0.5f;

    size_t pos = (size_t)(b * h + i) * wd + j;
    __half2 p0 = __floats2half2_rn(ll, lh);
    __half2 p1 = __floats2half2_rn(hl, hh);
    uint2 v; v.x = *(uint32_t*)&p0; v.y = *(uint32_t*)&p1;
    *(uint2*)(oh16 + pos * C4 + c * 4) = v;
    oLL[pos * NC + c] = ll;
}

// NHWC-32 input DWT (levels 2,3)
__global__ void dwt_k(const float* __restrict__ src, int wIn,
                      __half* __restrict__ oh16, float* __restrict__ oLL, int h, int w) {
    long total = (long)NB * h * w * NC;
    long idx = (long)blockIdx.x * 256 + threadIdx.x;
    if (idx >= total) return;
    int c = (int)(idx & 31);
    long t = idx >> 5;
    int j = (int)(t % w); t /= w;
    int i = (int)(t % h);
    int b = (int)(t / h);

    const float* s = src + (((size_t)b * (2 * h) + 2 * i) * (size_t)wIn + 2 * j) * NC + c;
    float a = s[0], bb = s[NC], cc = s[(size_t)wIn * NC], dd = s[(size_t)wIn * NC + NC];
    float ll = (a + bb + cc + dd) * 0.5f;
    float lh = (a - bb + cc - dd) * 0.5f;
    float hl = (a + bb - cc - dd) * 0.5f;
    float hh = (a - bb - cc + dd) * 0.5f;

    size_t pos = (size_t)(b * h + i) * w + j;
    __half2 p0 = __floats2half2_rn(ll, lh);
    __half2 p1 = __floats2half2_rn(hl, hh);
    uint2 v; v.x = *(uint32_t*)&p0; v.y = *(uint32_t*)&p1;
    *(uint2*)(oh16 + pos * C4 + c * 4) = v;
    if (oLL) oLL[pos * NC + c] = ll;
}

// ================= IDWT =================
__global__ void idwt_k(const float* __restrict__ y, const float* __restrict__ addll,
                       float* __restrict__ out, int h, int w, int finalOut,
                       const float* __restrict__ bias) {
    long total = (long)NB * h * w * NC;
    long idx = (long)blockIdx.x * 256 + threadIdx.x;
    if (idx >= total) return;
    int c = (int)(idx & 31);
    long t = idx >> 5;
    int j = (int)(t % w); t /= w;
    int i = (int)(t % h);
    int b = (int)(t / h);

    size_t pos = (size_t)(b * h + i) * w + j;
    float4 s = *(const float4*)(y + pos * C4 + c * 4);
    float ll = s.x, lh = s.y, hl = s.z, hh = s.w;
    if (addll) ll += addll[pos * NC + c];
    float a  = (ll + lh + hl + hh) * 0.5f;
    float bb = (ll - lh + hl - hh) * 0.5f;
    float cc = (ll + lh - hl - hh) * 0.5f;
    float dd = (ll - lh - hl + hh) * 0.5f;

    int H = 2 * h, W = 2 * w;
    if (finalOut) {
        float bv = bias[c];
        float* o = out + (((size_t)(b * NC + c)) * H + 2 * i) * (size_t)W + 2 * j;
        o[0] = a + bv; o[1] = bb + bv;
        o[W] = cc + bv; o[W + 1] = dd + bv;
    } else {
        float* o = out + (((size_t)b * H + 2 * i) * (size_t)W + 2 * j) * NC + c;
        o[0] = a; o[NC] = bb;
        o[(size_t)W * NC] = cc; o[(size_t)W * NC + NC] = dd;
    }
}

// ================= conv: halo-A + B-ring, 256 threads, 8 warps of 64x32 =================
__global__ __launch_bounds__(256, 2)
void conv_mma(const __half* __restrict__ a1, float* __restrict__ y1,
              const __half* __restrict__ a2, float* __restrict__ y2,
              const __half* __restrict__ a3, float* __restrict__ y3,
              const __half* __restrict__ wgt) {
    extern __shared__ __align__(128) char smem[];
    const uint32_t haloB = smem_u32(smem);
    const uint32_t bBase = haloB + HALO_BYTES;

    // ---- decode level / batch / tile ----
    int bid = blockIdx.x;
    const __half* act; float* y; int h, b, ti, tj;
    if (bid < NT1)            { act = a1; y = y1; h = H1; b = bid / 98; int r = bid % 98; ti = r / 7;  tj = r % 7; }
    else if (bid < NT1 + NT2) { int t = bid - NT1;       act = a2; y = y2; h = H2; b = t / 28; int r = t % 28; ti = r / 4; tj = r % 4; }
    else                      { int t = bid - NT1 - NT2; act = a3; y = y3; h = H3; b = t / 8;  int r = t % 8;  ti = r / 2; tj = r % 2; }
    const int w = h;
    const int oh0 = ti * 8, ow0 = tj * 16;

    const int tid = threadIdx.x;
    const int lane = tid & 31;
    const int wid = tid >> 5;
    const int wm = wid & 1;        // 2 warps along M (64 rows)
    const int wn = wid >> 1;       // 4 warps along N (32 cols)

    // ---- halo load: 10x18 cells x 16 chunks = 2880 x 16B ----
    {
        const size_t actB = (size_t)b * h * w * C4;
#pragma unroll
        for (int it = 0; it < 12; it++) {
            int idx = it * 256 + tid;
            if (idx < 2880) {
                int cell = idx >> 4, q = idx & 15;
                int hr = cell / 18, hc = cell - hr * 18;
                int ih = oh0 + hr - 1, iw = ow0 + hc - 1;
                bool v = ((unsigned)ih < (unsigned)h) && ((unsigned)iw < (unsigned)w);
                const char* src = (const char*)(act + actB + ((size_t)ih * w + iw) * C4 + q * 8);
                uint32_t dst = haloB + (uint32_t)cell * 256 +
                               (uint32_t)((((q & 7) ^ (cell & 7)) + (q & 8)) << 4);
                cp16(dst, src, v ? 16u : 0u);
            }
        }
    }

    // ---- B chunk loader: chunk ch -> tap=ch>>1, kc=ch&1 ; 1024 x 16B ----
    auto load_b = [&](int ch, uint32_t st) {
        int tap = ch >> 1, kc = ch & 1;
        const __half* wt = wgt + ((size_t)tap * C4) * C4 + kc * 64;
#pragma unroll
        for (int it = 0; it < 4; it++) {
            int idx = it * 256 + tid;
            int n = idx >> 3, q = idx & 7;
            const char* src = (const char*)(wt + (size_t)n * C4 + q * 8);
            cp16(st + (uint32_t)n * 128 + (uint32_t)((q ^ (n & 7)) << 4), src, 16u);
        }
    };

    // ---- ldmatrix geometry ----
    const int aSeg = lane >> 4;            // A k-seg half
    const int aJ = lane & 15;              // A: j within tile row
    uint32_t bRowOff[2]; int bSx[2];
#pragma unroll
    for (int bt = 0; bt < 2; bt++) {
        int rowB = wn * 32 + bt * 16 + (lane & 7) + ((lane & 16) >> 1);
        bRowOff[bt] = (uint32_t)rowB * 128;
        bSx[bt] = rowB & 7;
    }
    const int bSeg = (lane >> 3) & 1;

    float acc[4][4][4];
#pragma unroll
    for (int i = 0; i < 4; i++)
#pragma unroll
        for (int j = 0; j < 4; j++)
#pragma unroll
            for (int q = 0; q < 4; q++) acc[i][j][q] = 0.0f;

    load_b(0, bBase);
    CP_COMMIT();                               // group0 = halo + B0
    load_b(1, bBase + B_STAGE);
    CP_COMMIT();

    uint32_t stC = bBase;
    uint32_t stL = bBase + 2u * B_STAGE;
    const uint32_t stEnd = bBase + 3u * B_STAGE;

#pragma unroll 1
    for (int ch = 0; ch < NCHUNK; ch++) {
        CP_WAIT1();
        __syncthreads();
        if (ch + 2 < NCHUNK) load_b(ch + 2, stL);
        CP_COMMIT();

        const int tap = ch >> 1;
        const int kc  = ch & 1;
        const int kh = tap / 3;               // 0..2 (halo origin already -1)
        const int kw = tap - kh * 3;

        // per-mt A cell (lane-dependent), fixed for this chunk
        uint32_t aOff[4]; int aC7[4];
#pragma unroll
        for (int mt = 0; mt < 4; mt++) {
            int cell = (wm * 4 + mt + kh) * 18 + kw + aJ;
            aOff[mt] = haloB + (uint32_t)cell * 256;
            aC7[mt] = cell & 7;
        }

#pragma unroll
        for (int ks = 0; ks < 4; ks++) {
            uint32_t af[4][4];
            const int qa = kc * 8 + ks * 2 + aSeg;
#pragma unroll
            for (int mt = 0; mt < 4; mt++) {
                uint32_t addr = aOff[mt] +
                    (uint32_t)((((qa & 7) ^ aC7[mt]) + (qa & 8)) << 4);
                ldsm_x4(af[mt][0], af[mt][1], af[mt][2], af[mt][3], addr);
            }
            uint32_t bf[4][2];
#pragma unroll
            for (int bt = 0; bt < 2; bt++) {
                uint32_t r0, r1, r2, r3;
                ldsm_x4(r0, r1, r2, r3,
                        stC + bRowOff[bt] + (uint32_t)(((ks * 2 + bSeg) ^ bSx[bt]) << 4));
                bf[bt * 2 + 0][0] = r0; bf[bt * 2 + 0][1] = r1;
                bf[bt * 2 + 1][0] = r2; bf[bt * 2 + 1][1] = r3;
            }
#pragma unroll
            for (int mt = 0; mt < 4; mt++)
#pragma unroll
                for (int nt = 0; nt < 4; nt++)
                    mma16816(acc[mt][nt], af[mt], bf[nt]);
        }

        stC += B_STAGE; if (stC >= stEnd) stC = bBase;
        stL += B_STAGE; if (stL >= stEnd) stL = bBase;
    }

    // ---- epilogue: thread rows j=(lane>>2), j+8 at i=wm*4+mt ----
    const int jc = lane >> 2;
    const int nBase = wn * 32 + (lane & 3) * 2;
#pragma unroll
    for (int mt = 0; mt < 4; mt++) {
        int oh = oh0 + wm * 4 + mt;
        int ow = ow0 + jc;
        bool ohv = oh < h;
        bool v0 = ohv && (ow < w);
        bool v1 = ohv && (ow + 8 < w);
        float* d0 = y + ((size_t)(b * h + oh) * w + ow) * C4 + nBase;
        float* d1 = d0 + 8 * C4;
#pragma unroll
        for (int nt = 0; nt < 4; nt++) {
            if (v0) *(float2*)(d0 + nt * 8) = make_float2(acc[mt][nt][0], acc[mt][nt][1]);
            if (v1) *(float2*)(d1 + nt * 8) = make_float2(acc[mt][nt][2], acc[mt][nt][3]);
        }
    }
}

// ================= launch =================
static inline int cdiv(long a, int b) { return (int)((a + b - 1) / b); }

extern "C" void kernel_launch(void* const* d_in, const int* in_sizes, int n_in,
                              void* d_out, int out_size) {
    const float* x    = (const float*)d_in[0];
    const float* wgt  = (const float*)d_in[1];
    const float* bias = (const float*)d_in[2];
    float* out = (float*)d_out;

    __half *a1, *a2, *a3, *wh;
    float *ll1, *ll2, *y1, *y2, *y3, *r2, *r1;
    cudaGetSymbolAddress((void**)&a1, g_a1);
    cudaGetSymbolAddress((void**)&a2, g_a2);
    cudaGetSymbolAddress((void**)&a3, g_a3);
    cudaGetSymbolAddress((void**)&wh, g_w);
    cudaGetSymbolAddress((void**)&ll1, g_ll1);  cudaGetSymbolAddress((void**)&ll2, g_ll2);
    cudaGetSymbolAddress((void**)&y1, g_y1);    cudaGetSymbolAddress((void**)&y2, g_y2);
    cudaGetSymbolAddress((void**)&y3, g_y3);
    cudaGetSymbolAddress((void**)&r2, g_r2);    cudaGetSymbolAddress((void**)&r1, g_r1);

    cudaFuncSetAttribute(conv_mma, cudaFuncAttributeMaxDynamicSharedMemorySize, SMEM_TOTAL);

    // 0: dwt level1 + fused weight convert
    dwt1w_k<<<WCONV_BLKS + cdiv((long)M1 * NC, 256), 256>>>(x, a1, ll1, wgt, wh);
    // 1: dwt level2
    dwt_k<<<cdiv((long)M2 * NC, 256), 256>>>(ll1, H1, a2, ll2, H2, H2);
    // 2: dwt level3
    dwt_k<<<cdiv((long)M3 * NC, 256), 256>>>(ll2, H2, a3, nullptr, H3, H3);
    // 3: all convs (profiled index)
    conv_mma<<<NT1 + NT2 + NT3, 256, SMEM_TOTAL>>>(a1, y1, a2, y2, a3, y3, wh);
    // 4-6: reconstruction
    idwt_k<<<cdiv((long)M3 * NC, 256), 256>>>(y3, nullptr, r2, H3, H3, 0, nullptr);
    idwt_k<<<cdiv((long)M2 * NC, 256), 256>>>(y2, r2, r1, H2, H2, 0, nullptr);
    idwt_k<<<cdiv((long)M1 * NC, 256), 256>>>(y1, r1, out, H1, H1, 1, bias);
}

// round 10
// speedup vs baseline: 1.9085x; 1.4601x over previous
#include <cuda_runtime.h>
#include <cuda_fp16.h>
#include <cstdint>
#include <cstddef>

// ================= problem constants =================
#define NB 8
#define NC 32
#define C4 128
#define H1 112
#define H2 56
#define H3 28
#define M1 (NB * H1 * H1)
#define M2 (NB * H2 * H2)
#define M3 (NB * H3 * H3)

// spatial tile: 8 rows (i) x 16 cols (j) = 128 M-rows per block
#define NT1 (NB * 14 * 7)   // 784
#define NT2 (NB * 7 * 4)    // 224
#define NT3 (NB * 4 * 2)    // 64

#define NCHUNK 18           // 9 taps x 2 kc halves (BK=64)
#define HALO_BYTES 46080    // 10*18 cells * 256B
#define B_STAGE 16384       // 128 n-rows x 128B
#define NPIPE 3
#define SMEM_TOTAL (HALO_BYTES + NPIPE * B_STAGE)   // 95232 -> 2 CTAs/SM

#define WCONV_BLKS ((9 * C4 * C4) / 256)   // 576
#define DWT1_BLKS (NB * H1 * 2)            // 1792 (b, i, jhalf)

// ================= scratch =================
__device__ __half g_a1[(size_t)M1 * C4];
__device__ __half g_a2[(size_t)M2 * C4];
__device__ __half g_a3[(size_t)M3 * C4];
__device__ float g_ll1[(size_t)M1 * NC];
__device__ float g_ll2[(size_t)M2 * NC];
__device__ float g_y1 [(size_t)M1 * C4];
__device__ float g_y2 [(size_t)M2 * C4];
__device__ float g_y3 [(size_t)M3 * C4];
__device__ float g_r2 [(size_t)M2 * NC];
__device__ float g_r1 [(size_t)M1 * NC];
__device__ __half g_w[(size_t)9 * C4 * C4];    // [tap][n][ic]

// ================= helpers =================
__device__ __forceinline__ uint32_t smem_u32(const void* p) {
    uint32_t a;
    asm("{ .reg .u64 t; cvta.to.shared.u64 t, %1; cvt.u32.u64 %0, t; }" : "=r"(a) : "l"(p));
    return a;
}
__device__ __forceinline__ void ldsm_x4(uint32_t& r0, uint32_t& r1, uint32_t& r2, uint32_t& r3,
                                        uint32_t addr) {
    asm volatile("ldmatrix.sync.aligned.m8n8.x4.shared.b16 {%0,%1,%2,%3}, [%4];"
                 : "=r"(r0), "=r"(r1), "=r"(r2), "=r"(r3) : "r"(addr));
}
__device__ __forceinline__ void mma16816(float* c, const uint32_t* a, const uint32_t* b) {
    asm volatile(
        "mma.sync.aligned.m16n8k16.row.col.f32.f16.f16.f32 "
        "{%0,%1,%2,%3}, {%4,%5,%6,%7}, {%8,%9}, {%0,%1,%2,%3};"
        : "+f"(c[0]), "+f"(c[1]), "+f"(c[2]), "+f"(c[3])
        : "r"(a[0]), "r"(a[1]), "r"(a[2]), "r"(a[3]), "r"(b[0]), "r"(b[1]));
}
__device__ __forceinline__ void cp16(uint32_t saddr, const void* gptr, uint32_t srcsz) {
    size_t ga = __cvta_generic_to_global(gptr);
    asm volatile("cp.async.ca.shared.global [%0], [%1], 16, %2;"
                 :: "r"(saddr), "l"(ga), "r"(srcsz) : "memory");
}
#define CP_COMMIT() asm volatile("cp.async.commit_group;" ::: "memory")
#define CP_WAIT1()  asm volatile("cp.async.wait_group 1;" ::: "memory")

// ================= DWT level1 (NCHW coalesced via smem transpose) + weight convert =================
__global__ void dwt1w_k(const float* __restrict__ x, __half* __restrict__ oh16,
                        float* __restrict__ oLL, const float* __restrict__ w,
                        __half* __restrict__ wh) {
    if (blockIdx.x < WCONV_BLKS) {
        int idx = blockIdx.x * 256 + threadIdx.x;
        int tap = idx / (C4 * C4);
        int rem = idx - tap * C4 * C4;
        int o = rem >> 7, ic = rem & 127;
        wh[idx] = __float2half(w[((size_t)o * C4 + ic) * 9 + tap]);
        return;
    }
    __shared__ float srow[2][NC][113];     // 112 input cols (half row), stride 113
    int blk = blockIdx.x - WCONV_BLKS;
    int jh = blk & 1;
    int i  = (blk >> 1) % H1;
    int b  = (blk >> 1) / H1;
    const int tid = threadIdx.x;

    // phase 1: coalesced NCHW reads -> smem (2 rows x 32 ch x 112 cols)
    const float* xb = x + (size_t)b * NC * 224 * 224 + (size_t)jh * 112;
#pragma unroll
    for (int it = 0; it < 7; it++) {
        int t = it * 256 + tid;            // 1792 float4 total
        int f4 = t % 28;
        int c  = (t / 28) & 31;
        int r  = t / (28 * 32);
        float4 v = *(const float4*)(xb + ((size_t)c * 224 + (2 * i + r)) * 224 + f4 * 4);
        float* d = &srow[r][c][f4 * 4];
        d[0] = v.x; d[1] = v.y; d[2] = v.z; d[3] = v.w;
    }
    __syncthreads();

    // phase 2: compute + coalesced NHWC writes
    const int c = tid & 31;
#pragma unroll
    for (int l = 0; l < 7; l++) {
        int jl = (tid >> 5) + l * 8;       // 0..55
        float a  = srow[0][c][2 * jl];
        float bb = srow[0][c][2 * jl + 1];
        float cc = srow[1][c][2 * jl];
        float dd = srow[1][c][2 * jl + 1];
        float ll = (a + bb + cc + dd) * 0.5f;
        float lh = (a - bb + cc - dd) * 0.5f;
        float hl = (a + bb - cc - dd) * 0.5f;
        float hh = (a - bb - cc + dd) * 0.5f;
        int j = jh * 56 + jl;
        size_t pos = (size_t)(b * H1 + i) * H1 + j;
        __half2 p0 = __floats2half2_rn(ll, lh);
        __half2 p1 = __floats2half2_rn(hl, hh);
        uint2 v; v.x = *(uint32_t*)&p0; v.y = *(uint32_t*)&p1;
        *(uint2*)(oh16 + pos * C4 + c * 4) = v;
        oLL[pos * NC + c] = ll;
    }
}

// NHWC-32 input DWT (levels 2,3)
__global__ void dwt_k(const float* __restrict__ src, int wIn,
                      __half* __restrict__ oh16, float* __restrict__ oLL, int h, int w) {
    long total = (long)NB * h * w * NC;
    long idx = (long)blockIdx.x * 256 + threadIdx.x;
    if (idx >= total) return;
    int c = (int)(idx & 31);
    long t = idx >> 5;
    int j = (int)(t % w); t /= w;
    int i = (int)(t % h);
    int b = (int)(t / h);

    const float* s = src + (((size_t)b * (2 * h) + 2 * i) * (size_t)wIn + 2 * j) * NC + c;
    float a = s[0], bb = s[NC], cc = s[(size_t)wIn * NC], dd = s[(size_t)wIn * NC + NC];
    float ll = (a + bb + cc + dd) * 0.5f;
    float lh = (a - bb + cc - dd) * 0.5f;
    float hl = (a + bb - cc - dd) * 0.5f;
    float hh = (a - bb - cc + dd) * 0.5f;

    size_t pos = (size_t)(b * h + i) * w + j;
    __half2 p0 = __floats2half2_rn(ll, lh);
    __half2 p1 = __floats2half2_rn(hl, hh);
    uint2 v; v.x = *(uint32_t*)&p0; v.y = *(uint32_t*)&p1;
    *(uint2*)(oh16 + pos * C4 + c * 4) = v;
    if (oLL) oLL[pos * NC + c] = ll;
}

// ================= IDWT mid (NHWC-32 out) =================
__global__ void idwt_k(const float* __restrict__ y, const float* __restrict__ addll,
                       float* __restrict__ out, int h, int w) {
    long total = (long)NB * h * w * NC;
    long idx = (long)blockIdx.x * 256 + threadIdx.x;
    if (idx >= total) return;
    int c = (int)(idx & 31);
    long t = idx >> 5;
    int j = (int)(t % w); t /= w;
    int i = (int)(t % h);
    int b = (int)(t / h);

    size_t pos = (size_t)(b * h + i) * w + j;
    float4 s = *(const float4*)(y + pos * C4 + c * 4);
    float ll = s.x, lh = s.y, hl = s.z, hh = s.w;
    if (addll) ll += addll[pos * NC + c];
    float a  = (ll + lh + hl + hh) * 0.5f;
    float bb = (ll - lh + hl - hh) * 0.5f;
    float cc = (ll + lh - hl - hh) * 0.5f;
    float dd = (ll - lh - hl + hh) * 0.5f;

    int W = 2 * w;
    float* o = out + (((size_t)b * (2 * h) + 2 * i) * (size_t)W + 2 * j) * NC + c;
    o[0] = a; o[NC] = bb;
    o[(size_t)W * NC] = cc; o[(size_t)W * NC + NC] = dd;
}

// ================= IDWT final (NCHW coalesced via smem transpose) =================
__global__ void idwt1f_k(const float* __restrict__ y, const float* __restrict__ addll,
                         float* __restrict__ out, const float* __restrict__ bias) {
    __shared__ float orow[2][NC][113];     // 2 output rows x 32 ch x 112 cols (half)
    int blk = blockIdx.x;
    int jh = blk & 1;
    int i  = (blk >> 1) % H1;
    int b  = (blk >> 1) / H1;
    const int tid = threadIdx.x;
    const int c = tid & 31;
    const float bv = bias[c];

    // phase 1: coalesced NHWC reads -> compute -> smem in NCHW-friendly layout
#pragma unroll
    for (int l = 0; l < 7; l++) {
        int jl = (tid >> 5) + l * 8;       // 0..55
        int j = jh * 56 + jl;
        size_t pos = (size_t)(b * H1 + i) * H1 + j;
        float4 s = *(const float4*)(y + pos * C4 + c * 4);
        float ll = s.x + addll[pos * NC + c];
        float lh = s.y, hl = s.z, hh = s.w;
        float a  = (ll + lh + hl + hh) * 0.5f + bv;
        float bb = (ll - lh + hl - hh) * 0.5f + bv;
        float cc = (ll + lh - hl - hh) * 0.5f + bv;
        float dd = (ll - lh - hl + hh) * 0.5f + bv;
        orow[0][c][2 * jl]     = a;
        orow[0][c][2 * jl + 1] = bb;
        orow[1][c][2 * jl]     = cc;
        orow[1][c][2 * jl + 1] = dd;
    }
    __syncthreads();

    // phase 2: coalesced NCHW writes
    float* ob = out + (size_t)b * NC * 224 * 224 + (size_t)jh * 112;
#pragma unroll
    for (int it = 0; it < 7; it++) {
        int t = it * 256 + tid;            // 1792 float4 total
        int f4 = t % 28;
        int cc2 = (t / 28) & 31;
        int r  = t / (28 * 32);
        const float* srcp = &orow[r][cc2][f4 * 4];
        float4 v = make_float4(srcp[0], srcp[1], srcp[2], srcp[3]);
        *(float4*)(ob + ((size_t)cc2 * 224 + (2 * i + r)) * 224 + f4 * 4) = v;
    }
}

// ================= conv: halo-A + B-ring, 256 threads, 8 warps of 64x32 =================
__global__ __launch_bounds__(256, 2)
void conv_mma(const __half* __restrict__ a1, float* __restrict__ y1,
              const __half* __restrict__ a2, float* __restrict__ y2,
              const __half* __restrict__ a3, float* __restrict__ y3,
              const __half* __restrict__ wgt) {
    extern __shared__ __align__(128) char smem[];
    const uint32_t haloB = smem_u32(smem);
    const uint32_t bBase = haloB + HALO_BYTES;

    // ---- decode level / batch / tile ----
    int bid = blockIdx.x;
    const __half* act; float* y; int h, b, ti, tj;
    if (bid < NT1)            { act = a1; y = y1; h = H1; b = bid / 98; int r = bid % 98; ti = r / 7;  tj = r % 7; }
    else if (bid < NT1 + NT2) { int t = bid - NT1;       act = a2; y = y2; h = H2; b = t / 28; int r = t % 28; ti = r / 4; tj = r % 4; }
    else                      { int t = bid - NT1 - NT2; act = a3; y = y3; h = H3; b = t / 8;  int r = t % 8;  ti = r / 2; tj = r % 2; }
    const int w = h;
    const int oh0 = ti * 8, ow0 = tj * 16;

    const int tid = threadIdx.x;
    const int lane = tid & 31;
    const int wid = tid >> 5;
    const int wm = wid & 1;        // 2 warps along M (64 rows)
    const int wn = wid >> 1;       // 4 warps along N (32 cols)

    // ---- halo load: 10x18 cells x 16 chunks = 2880 x 16B ----
    {
        const size_t actB = (size_t)b * h * w * C4;
#pragma unroll
        for (int it = 0; it < 12; it++) {
            int idx = it * 256 + tid;
            if (idx < 2880) {
                int cell = idx >> 4, q = idx & 15;
                int hr = cell / 18, hc = cell - hr * 18;
                int ih = oh0 + hr - 1, iw = ow0 + hc - 1;
                bool v = ((unsigned)ih < (unsigned)h) && ((unsigned)iw < (unsigned)w);
                const char* src = (const char*)(act + actB + ((size_t)ih * w + iw) * C4 + q * 8);
                uint32_t dst = haloB + (uint32_t)cell * 256 +
                               (uint32_t)((((q & 7) ^ (cell & 7)) + (q & 8)) << 4);
                cp16(dst, src, v ? 16u : 0u);
            }
        }
    }

    // ---- B chunk loader ----
    auto load_b = [&](int ch, uint32_t st) {
        int tap = ch >> 1, kc = ch & 1;
        const __half* wt = wgt + ((size_t)tap * C4) * C4 + kc * 64;
#pragma unroll
        for (int it = 0; it < 4; it++) {
            int idx = it * 256 + tid;
            int n = idx >> 3, q = idx & 7;
            const char* src = (const char*)(wt + (size_t)n * C4 + q * 8);
            cp16(st + (uint32_t)n * 128 + (uint32_t)((q ^ (n & 7)) << 4), src, 16u);
        }
    };

    // ---- ldmatrix geometry ----
    const int aSeg = lane >> 4;
    const int aJ = lane & 15;
    uint32_t bRowOff[2]; int bSx[2];
#pragma unroll
    for (int bt = 0; bt < 2; bt++) {
        int rowB = wn * 32 + bt * 16 + (lane & 7) + ((lane & 16) >> 1);
        bRowOff[bt] = (uint32_t)rowB * 128;
        bSx[bt] = rowB & 7;
    }
    const int bSeg = (lane >> 3) & 1;

    float acc[4][4][4];
#pragma unroll
    for (int i = 0; i < 4; i++)
#pragma unroll
        for (int j = 0; j < 4; j++)
#pragma unroll
            for (int q = 0; q < 4; q++) acc[i][j][q] = 0.0f;

    load_b(0, bBase);
    CP_COMMIT();
    load_b(1, bBase + B_STAGE);
    CP_COMMIT();

    uint32_t stC = bBase;
    uint32_t stL = bBase + 2u * B_STAGE;
    const uint32_t stEnd = bBase + 3u * B_STAGE;

#pragma unroll 1
    for (int ch = 0; ch < NCHUNK; ch++) {
        CP_WAIT1();
        __syncthreads();
        if (ch + 2 < NCHUNK) load_b(ch + 2, stL);
        CP_COMMIT();

        const int tap = ch >> 1;
        const int kc  = ch & 1;
        const int kh = tap / 3;
        const int kw = tap - kh * 3;

        uint32_t aOff[4]; int aC7[4];
#pragma unroll
        for (int mt = 0; mt < 4; mt++) {
            int cell = (wm * 4 + mt + kh) * 18 + kw + aJ;
            aOff[mt] = haloB + (uint32_t)cell * 256;
            aC7[mt] = cell & 7;
        }

#pragma unroll
        for (int ks = 0; ks < 4; ks++) {
            uint32_t af[4][4];
            const int qa = kc * 8 + ks * 2 + aSeg;
#pragma unroll
            for (int mt = 0; mt < 4; mt++) {
                uint32_t addr = aOff[mt] +
                    (uint32_t)((((qa & 7) ^ aC7[mt]) + (qa & 8)) << 4);
                ldsm_x4(af[mt][0], af[mt][1], af[mt][2], af[mt][3], addr);
            }
            uint32_t bf[4][2];
#pragma unroll
            for (int bt = 0; bt < 2; bt++) {
                uint32_t r0, r1, r2, r3;
                ldsm_x4(r0, r1, r2, r3,
                        stC + bRowOff[bt] + (uint32_t)(((ks * 2 + bSeg) ^ bSx[bt]) << 4));
                bf[bt * 2 + 0][0] = r0; bf[bt * 2 + 0][1] = r1;
                bf[bt * 2 + 1][0] = r2; bf[bt * 2 + 1][1] = r3;
            }
#pragma unroll
            for (int mt = 0; mt < 4; mt++)
#pragma unroll
                for (int nt = 0; nt < 4; nt++)
                    mma16816(acc[mt][nt], af[mt], bf[nt]);
        }

        stC += B_STAGE; if (stC >= stEnd) stC = bBase;
        stL += B_STAGE; if (stL >= stEnd) stL = bBase;
    }

    // ---- epilogue ----
    const int jc = lane >> 2;
    const int nBase = wn * 32 + (lane & 3) * 2;
#pragma unroll
    for (int mt = 0; mt < 4; mt++) {
        int oh = oh0 + wm * 4 + mt;
        int ow = ow0 + jc;
        bool ohv = oh < h;
        bool v0 = ohv && (ow < w);
        bool v1 = ohv && (ow + 8 < w);
        float* d0 = y + ((size_t)(b * h + oh) * w + ow) * C4 + nBase;
        float* d1 = d0 + 8 * C4;
#pragma unroll
        for (int nt = 0; nt < 4; nt++) {
            if (v0) *(float2*)(d0 + nt * 8) = make_float2(acc[mt][nt][0], acc[mt][nt][1]);
            if (v1) *(float2*)(d1 + nt * 8) = make_float2(acc[mt][nt][2], acc[mt][nt][3]);
        }
    }
}

// ================= launch =================
static inline int cdiv(long a, int b) { return (int)((a + b - 1) / b); }

extern "C" void kernel_launch(void* const* d_in, const int* in_sizes, int n_in,
                              void* d_out, int out_size) {
    const float* x    = (const float*)d_in[0];
    const float* wgt  = (const float*)d_in[1];
    const float* bias = (const float*)d_in[2];
    float* out = (float*)d_out;

    __half *a1, *a2, *a3, *wh;
    float *ll1, *ll2, *y1, *y2, *y3, *r2, *r1;
    cudaGetSymbolAddress((void**)&a1, g_a1);
    cudaGetSymbolAddress((void**)&a2, g_a2);
    cudaGetSymbolAddress((void**)&a3, g_a3);
    cudaGetSymbolAddress((void**)&wh, g_w);
    cudaGetSymbolAddress((void**)&ll1, g_ll1);  cudaGetSymbolAddress((void**)&ll2, g_ll2);
    cudaGetSymbolAddress((void**)&y1, g_y1);    cudaGetSymbolAddress((void**)&y2, g_y2);
    cudaGetSymbolAddress((void**)&y3, g_y3);
    cudaGetSymbolAddress((void**)&r2, g_r2);    cudaGetSymbolAddress((void**)&r1, g_r1);

    cudaFuncSetAttribute(conv_mma, cudaFuncAttributeMaxDynamicSharedMemorySize, SMEM_TOTAL);

    // 0: dwt level1 (coalesced transpose) + fused weight convert
    dwt1w_k<<<WCONV_BLKS + DWT1_BLKS, 256>>>(x, a1, ll1, wgt, wh);
    // 1: dwt level2
    dwt_k<<<cdiv((long)M2 * NC, 256), 256>>>(ll1, H1, a2, ll2, H2, H2);
    // 2: dwt level3
    dwt_k<<<cdiv((long)M3 * NC, 256), 256>>>(ll2, H2, a3, nullptr, H3, H3);
    // 3: all convs (profiled index)
    conv_mma<<<NT1 + NT2 + NT3, 256, SMEM_TOTAL>>>(a1, y1, a2, y2, a3, y3, wh);
    // 4: idwt level3 -> r2
    idwt_k<<<cdiv((long)M3 * NC, 256), 256>>>(y3, nullptr, r2, H3, H3);
    // 5: idwt level2 -> r1
    idwt_k<<<cdiv((long)M2 * NC, 256), 256>>>(y2, r2, r1, H2, H2);
    // 6: idwt level1 -> out (coalesced transpose, bias)
    idwt1f_k<<<DWT1_BLKS, 256>>>(y1, r1, out, bias);
}

// round 11
// speedup vs baseline: 2.1426x; 1.1227x over previous
#include <cuda_runtime.h>
#include <cuda_fp16.h>
#include <cstdint>
#include <cstddef>

// ================= problem constants =================
#define NB 8
#define NC 32
#define C4 128
#define H1 112
#define H2 56
#define H3 28
#define M1 (NB * H1 * H1)
#define M2 (NB * H2 * H2)
#define M3 (NB * H3 * H3)

// conv spatial tile: 8 x 16 = 128 M-rows per block
#define NT1 (NB * 14 * 7)   // 784
#define NT2 (NB * 7 * 4)    // 224
#define NT3 (NB * 4 * 2)    // 64

#define NCHUNK 18           // 9 taps x 2 kc halves (BK=64)
#define HALO_BYTES 46080    // 10*18 cells * 256B
#define B_STAGE 16384
#define NPIPE 3
#define SMEM_TOTAL (HALO_BYTES + NPIPE * B_STAGE)   // 95232 -> 2 CTAs/SM

#define WCONV_BLKS ((9 * C4 * C4) / 256)   // 576
#define CASC_BLKS (NB * 28 * 2)            // 448 (b, t, jhalf)

// ================= scratch =================
__device__ __half g_a1[(size_t)M1 * C4];
__device__ __half g_a2[(size_t)M2 * C4];
__device__ __half g_a3[(size_t)M3 * C4];
__device__ float g_y1 [(size_t)M1 * C4];
__device__ float g_y2 [(size_t)M2 * C4];
__device__ float g_y3 [(size_t)M3 * C4];
__device__ __half g_w[(size_t)9 * C4 * C4];    // [tap][n][ic]

// ================= helpers =================
__device__ __forceinline__ uint32_t smem_u32(const void* p) {
    uint32_t a;
    asm("{ .reg .u64 t; cvta.to.shared.u64 t, %1; cvt.u32.u64 %0, t; }" : "=r"(a) : "l"(p));
    return a;
}
__device__ __forceinline__ void ldsm_x4(uint32_t& r0, uint32_t& r1, uint32_t& r2, uint32_t& r3,
                                        uint32_t addr) {
    asm volatile("ldmatrix.sync.aligned.m8n8.x4.shared.b16 {%0,%1,%2,%3}, [%4];"
                 : "=r"(r0), "=r"(r1), "=r"(r2), "=r"(r3) : "r"(addr));
}
__device__ __forceinline__ void mma16816(float* c, const uint32_t* a, const uint32_t* b) {
    asm volatile(
        "mma.sync.aligned.m16n8k16.row.col.f32.f16.f16.f32 "
        "{%0,%1,%2,%3}, {%4,%5,%6,%7}, {%8,%9}, {%0,%1,%2,%3};"
        : "+f"(c[0]), "+f"(c[1]), "+f"(c[2]), "+f"(c[3])
        : "r"(a[0]), "r"(a[1]), "r"(a[2]), "r"(a[3]), "r"(b[0]), "r"(b[1]));
}
__device__ __forceinline__ void cp16(uint32_t saddr, const void* gptr, uint32_t srcsz) {
    size_t ga = __cvta_generic_to_global(gptr);
    asm volatile("cp.async.cg.shared.global [%0], [%1], 16, %2;"
                 :: "r"(saddr), "l"(ga), "r"(srcsz) : "memory");
}
#define CP_COMMIT() asm volatile("cp.async.commit_group;" ::: "memory")
#define CP_WAIT1()  asm volatile("cp.async.wait_group 1;" ::: "memory")

// ================= fused DWT cascade (+ weight convert blocks) =================
__global__ void dwtall_k(const float* __restrict__ x, const float* __restrict__ w,
                         __half* __restrict__ wh, __half* __restrict__ a1,
                         __half* __restrict__ a2, __half* __restrict__ a3) {
    if (blockIdx.x < WCONV_BLKS) {
        int idx = blockIdx.x * 256 + threadIdx.x;
        int tap = idx / (C4 * C4);
        int rem = idx - tap * C4 * C4;
        int o = rem >> 7, ic = rem & 127;
        wh[idx] = __float2half(w[((size_t)o * C4 + ic) * 9 + tap]);
        return;
    }
    __shared__ float xrow[2][NC][113];
    __shared__ float ll1s[4][NC][57];
    __shared__ float ll2s[2][NC][29];

    int blk = blockIdx.x - WCONV_BLKS;
    int jh = blk & 1;
    int t  = (blk >> 1) % 28;
    int b  = (blk >> 1) / 28;
    const int tid = threadIdx.x;
    const int c = tid & 31;
    const float* xb = x + (size_t)b * NC * 224 * 224 + (size_t)jh * 112;

    // ---- level 1: 4 row-pairs ----
#pragma unroll 1
    for (int r = 0; r < 4; r++) {
#pragma unroll
        for (int it = 0; it < 7; it++) {
            int tt = it * 256 + tid;
            int f4 = tt % 28;
            int cc = (tt / 28) & 31;
            int rr = tt / (28 * 32);
            float4 v = *(const float4*)(xb + ((size_t)cc * 224 + (8 * t + 2 * r + rr)) * 224 + f4 * 4);
            float* d = &xrow[rr][cc][f4 * 4];
            d[0] = v.x; d[1] = v.y; d[2] = v.z; d[3] = v.w;
        }
        __syncthreads();
#pragma unroll
        for (int l = 0; l < 7; l++) {
            int jl = (tid >> 5) + l * 8;    // 0..55
            float a  = xrow[0][c][2 * jl],  bb = xrow[0][c][2 * jl + 1];
            float cc = xrow[1][c][2 * jl],  dd = xrow[1][c][2 * jl + 1];
            float ll = (a + bb + cc + dd) * 0.5f;
            float lh = (a - bb + cc - dd) * 0.5f;
            float hl = (a + bb - cc - dd) * 0.5f;
            float hh = (a - bb - cc + dd) * 0.5f;
            size_t pos = (size_t)(b * H1 + 4 * t + r) * H1 + jh * 56 + jl;
            __half2 p0 = __floats2half2_rn(ll, lh), p1 = __floats2half2_rn(hl, hh);
            uint2 v; v.x = *(uint32_t*)&p0; v.y = *(uint32_t*)&p1;
            *(uint2*)(a1 + pos * C4 + c * 4) = v;
            ll1s[r][c][jl] = ll;
        }
        __syncthreads();
    }

    // ---- level 2: 2 rows ----
#pragma unroll
    for (int l = 0; l < 7; l++) {
        int idx = (tid >> 5) + l * 8;       // 0..55
        int q = idx / 28, j2 = idx - q * 28;
        float a  = ll1s[2 * q][c][2 * j2],     bb = ll1s[2 * q][c][2 * j2 + 1];
        float cc = ll1s[2 * q + 1][c][2 * j2], dd = ll1s[2 * q + 1][c][2 * j2 + 1];
        float ll = (a + bb + cc + dd) * 0.5f;
        float lh = (a - bb + cc - dd) * 0.5f;
        float hl = (a + bb - cc - dd) * 0.5f;
        float hh = (a - bb - cc + dd) * 0.5f;
        size_t pos = (size_t)(b * H2 + 2 * t + q) * H2 + jh * 28 + j2;
        __half2 p0 = __floats2half2_rn(ll, lh), p1 = __floats2half2_rn(hl, hh);
        uint2 v; v.x = *(uint32_t*)&p0; v.y = *(uint32_t*)&p1;
        *(uint2*)(a2 + pos * C4 + c * 4) = v;
        ll2s[q][c][j2] = ll;
    }
    __syncthreads();

    // ---- level 3: 1 row (448 items) ----
#pragma unroll
    for (int l = 0; l < 2; l++) {
        int idx = tid + l * 256;
        if (idx < 448) {
            int c3 = idx & 31, j3 = idx >> 5;   // j3 0..13
            float a  = ll2s[0][c3][2 * j3], bb = ll2s[0][c3][2 * j3 + 1];
            float cc = ll2s[1][c3][2 * j3], dd = ll2s[1][c3][2 * j3 + 1];
            float ll = (a + bb + cc + dd) * 0.5f;
            float lh = (a - bb + cc - dd) * 0.5f;
            float hl = (a + bb - cc - dd) * 0.5f;
            float hh = (a - bb - cc + dd) * 0.5f;
            size_t pos = (size_t)(b * H3 + t) * H3 + jh * 14 + j3;
            __half2 p0 = __floats2half2_rn(ll, lh), p1 = __floats2half2_rn(hl, hh);
            uint2 v; v.x = *(uint32_t*)&p0; v.y = *(uint32_t*)&p1;
            *(uint2*)(a3 + pos * C4 + c3 * 4) = v;
        }
    }
}

// ================= fused IDWT cascade (bias + NCHW output) =================
__global__ void idwtall_k(const float* __restrict__ y1, const float* __restrict__ y2,
                          const float* __restrict__ y3, float* __restrict__ out,
                          const float* __restrict__ bias) {
    __shared__ float r2s[2][NC][29];
    __shared__ float r1s[4][NC][57];
    __shared__ float outs[2][NC][113];

    int blk = blockIdx.x;
    int jh = blk & 1;
    int t  = (blk >> 1) % 28;
    int b  = (blk >> 1) / 28;
    const int tid = threadIdx.x;
    const int c = tid & 31;
    const float bv = bias[c];

    // ---- idwt3: y3 row t -> r2 rows 0,1 (local) ----
#pragma unroll
    for (int l = 0; l < 2; l++) {
        int idx = tid + l * 256;
        if (idx < 448) {
            int c3 = idx & 31, j3 = idx >> 5;
            size_t pos = (size_t)(b * H3 + t) * H3 + jh * 14 + j3;
            float4 s = *(const float4*)(y3 + pos * C4 + c3 * 4);
            float ll = s.x, lh = s.y, hl = s.z, hh = s.w;
            float a  = (ll + lh + hl + hh) * 0.5f;
            float bb = (ll - lh + hl - hh) * 0.5f;
            float cc = (ll + lh - hl - hh) * 0.5f;
            float dd = (ll - lh - hl + hh) * 0.5f;
            r2s[0][c3][2 * j3]     = a;
            r2s[0][c3][2 * j3 + 1] = bb;
            r2s[1][c3][2 * j3]     = cc;
            r2s[1][c3][2 * j3 + 1] = dd;
        }
    }
    __syncthreads();

    // ---- idwt2: y2 rows 2t..2t+1 + r2 -> r1 rows 0..3 (local) ----
#pragma unroll
    for (int l = 0; l < 7; l++) {
        int idx = (tid >> 5) + l * 8;
        int q = idx / 28, j2 = idx - q * 28;
        size_t pos = (size_t)(b * H2 + 2 * t + q) * H2 + jh * 28 + j2;
        float4 s = *(const float4*)(y2 + pos * C4 + c * 4);
        float ll = s.x + r2s[q][c][j2];
        float lh = s.y, hl = s.z, hh = s.w;
        float a  = (ll + lh + hl + hh) * 0.5f;
        float bb = (ll - lh + hl - hh) * 0.5f;
        float cc = (ll + lh - hl - hh) * 0.5f;
        float dd = (ll - lh - hl + hh) * 0.5f;
        r1s[2 * q][c][2 * j2]         = a;
        r1s[2 * q][c][2 * j2 + 1]     = bb;
        r1s[2 * q + 1][c][2 * j2]     = cc;
        r1s[2 * q + 1][c][2 * j2 + 1] = dd;
    }
    __syncthreads();

    // ---- idwt1 + bias + NCHW transpose, 4 row-pairs ----
    float* ob = out + (size_t)b * NC * 224 * 224 + (size_t)jh * 112;
#pragma unroll 1
    for (int r = 0; r < 4; r++) {
#pragma unroll
        for (int l = 0; l < 7; l++) {
            int jl = (tid >> 5) + l * 8;
            size_t pos = (size_t)(b * H1 + 4 * t + r) * H1 + jh * 56 + jl;
            float4 s = *(const float4*)(y1 + pos * C4 + c * 4);
            float ll = s.x + r1s[r][c][jl];
            float lh = s.y, hl = s.z, hh = s.w;
            float a  = (ll + lh + hl + hh) * 0.5f + bv;
            float bb = (ll - lh + hl - hh) * 0.5f + bv;
            float cc = (ll + lh - hl - hh) * 0.5f + bv;
            float dd = (ll - lh - hl + hh) * 0.5f + bv;
            outs[0][c][2 * jl]     = a;
            outs[0][c][2 * jl + 1] = bb;
            outs[1][c][2 * jl]     = cc;
            outs[1][c][2 * jl + 1] = dd;
        }
        __syncthreads();
#pragma unroll
        for (int it = 0; it < 7; it++) {
            int tt = it * 256 + tid;
            int f4 = tt % 28;
            int c2 = (tt / 28) & 31;
            int rr = tt / (28 * 32);
            const float* sp = &outs[rr][c2][f4 * 4];
            float4 v = make_float4(sp[0], sp[1], sp[2], sp[3]);
            *(float4*)(ob + ((size_t)c2 * 224 + (8 * t + 2 * r + rr)) * 224 + f4 * 4) = v;
        }
        __syncthreads();
    }
}

// ================= conv: halo-A + B-ring, 256 threads, 8 warps of 64x32 =================
__global__ __launch_bounds__(256, 2)
void conv_mma(const __half* __restrict__ a1, float* __restrict__ y1,
              const __half* __restrict__ a2, float* __restrict__ y2,
              const __half* __restrict__ a3, float* __restrict__ y3,
              const __half* __restrict__ wgt) {
    extern __shared__ __align__(128) char smem[];
    const uint32_t haloB = smem_u32(smem);
    const uint32_t bBase = haloB + HALO_BYTES;

    int bid = blockIdx.x;
    const __half* act; float* y; int h, b, ti, tj;
    if (bid < NT1)            { act = a1; y = y1; h = H1; b = bid / 98; int r = bid % 98; ti = r / 7;  tj = r % 7; }
    else if (bid < NT1 + NT2) { int t = bid - NT1;       act = a2; y = y2; h = H2; b = t / 28; int r = t % 28; ti = r / 4; tj = r % 4; }
    else                      { int t = bid - NT1 - NT2; act = a3; y = y3; h = H3; b = t / 8;  int r = t % 8;  ti = r / 2; tj = r % 2; }
    const int w = h;
    const int oh0 = ti * 8, ow0 = tj * 16;

    const int tid = threadIdx.x;
    const int lane = tid & 31;
    const int wid = tid >> 5;
    const int wm = wid & 1;
    const int wn = wid >> 1;

    // ---- halo load ----
    {
        const size_t actB = (size_t)b * h * w * C4;
#pragma unroll
        for (int it = 0; it < 12; it++) {
            int idx = it * 256 + tid;
            if (idx < 2880) {
                int cell = idx >> 4, q = idx & 15;
                int hr = cell / 18, hc = cell - hr * 18;
                int ih = oh0 + hr - 1, iw = ow0 + hc - 1;
                bool v = ((unsigned)ih < (unsigned)h) && ((unsigned)iw < (unsigned)w);
                const char* src = (const char*)(act + actB + ((size_t)ih * w + iw) * C4 + q * 8);
                uint32_t dst = haloB + (uint32_t)cell * 256 +
                               (uint32_t)((((q & 7) ^ (cell & 7)) + (q & 8)) << 4);
                cp16(dst, src, v ? 16u : 0u);
            }
        }
    }

    auto load_b = [&](int ch, uint32_t st) {
        int tap = ch >> 1, kc = ch & 1;
        const __half* wt = wgt + ((size_t)tap * C4) * C4 + kc * 64;
#pragma unroll
        for (int it = 0; it < 4; it++) {
            int idx = it * 256 + tid;
            int n = idx >> 3, q = idx & 7;
            const char* src = (const char*)(wt + (size_t)n * C4 + q * 8);
            cp16(st + (uint32_t)n * 128 + (uint32_t)((q ^ (n & 7)) << 4), src, 16u);
        }
    };

    const int aSeg = lane >> 4;
    const int aJ = lane & 15;
    uint32_t bRowOff[2]; int bSx[2];
#pragma unroll
    for (int bt = 0; bt < 2; bt++) {
        int rowB = wn * 32 + bt * 16 + (lane & 7) + ((lane & 16) >> 1);
        bRowOff[bt] = (uint32_t)rowB * 128;
        bSx[bt] = rowB & 7;
    }
    const int bSeg = (lane >> 3) & 1;

    float acc[4][4][4];
#pragma unroll
    for (int i = 0; i < 4; i++)
#pragma unroll
        for (int j = 0; j < 4; j++)
#pragma unroll
            for (int q = 0; q < 4; q++) acc[i][j][q] = 0.0f;

    load_b(0, bBase);
    CP_COMMIT();
    load_b(1, bBase + B_STAGE);
    CP_COMMIT();

    uint32_t stC = bBase;
    uint32_t stL = bBase + 2u * B_STAGE;
    const uint32_t stEnd = bBase + 3u * B_STAGE;

#pragma unroll 1
    for (int ch = 0; ch < NCHUNK; ch++) {
        CP_WAIT1();
        __syncthreads();
        if (ch + 2 < NCHUNK) load_b(ch + 2, stL);
        CP_COMMIT();

        const int tap = ch >> 1;
        const int kc  = ch & 1;
        const int kh = tap / 3;
        const int kw = tap - kh * 3;

        uint32_t aOff[4]; int aC7[4];
#pragma unroll
        for (int mt = 0; mt < 4; mt++) {
            int cell = (wm * 4 + mt + kh) * 18 + kw + aJ;
            aOff[mt] = haloB + (uint32_t)cell * 256;
            aC7[mt] = cell & 7;
        }

#pragma unroll
        for (int ks = 0; ks < 4; ks++) {
            uint32_t af[4][4];
            const int qa = kc * 8 + ks * 2 + aSeg;
#pragma unroll
            for (int mt = 0; mt < 4; mt++) {
                uint32_t addr = aOff[mt] +
                    (uint32_t)((((qa & 7) ^ aC7[mt]) + (qa & 8)) << 4);
                ldsm_x4(af[mt][0], af[mt][1], af[mt][2], af[mt][3], addr);
            }
            uint32_t bf[4][2];
#pragma unroll
            for (int bt = 0; bt < 2; bt++) {
                uint32_t r0, r1, r2, r3;
                ldsm_x4(r0, r1, r2, r3,
                        stC + bRowOff[bt] + (uint32_t)(((ks * 2 + bSeg) ^ bSx[bt]) << 4));
                bf[bt * 2 + 0][0] = r0; bf[bt * 2 + 0][1] = r1;
                bf[bt * 2 + 1][0] = r2; bf[bt * 2 + 1][1] = r3;
            }
#pragma unroll
            for (int mt = 0; mt < 4; mt++)
#pragma unroll
                for (int nt = 0; nt < 4; nt++)
                    mma16816(acc[mt][nt], af[mt], bf[nt]);
        }

        stC += B_STAGE; if (stC >= stEnd) stC = bBase;
        stL += B_STAGE; if (stL >= stEnd) stL = bBase;
    }

    const int jc = lane >> 2;
    const int nBase = wn * 32 + (lane & 3) * 2;
#pragma unroll
    for (int mt = 0; mt < 4; mt++) {
        int oh = oh0 + wm * 4 + mt;
        int ow = ow0 + jc;
        bool ohv = oh < h;
        bool v0 = ohv && (ow < w);
        bool v1 = ohv && (ow + 8 < w);
        float* d0 = y + ((size_t)(b * h + oh) * w + ow) * C4 + nBase;
        float* d1 = d0 + 8 * C4;
#pragma unroll
        for (int nt = 0; nt < 4; nt++) {
            if (v0) *(float2*)(d0 + nt * 8) = make_float2(acc[mt][nt][0], acc[mt][nt][1]);
            if (v1) *(float2*)(d1 + nt * 8) = make_float2(acc[mt][nt][2], acc[mt][nt][3]);
        }
    }
}

// ================= launch =================
extern "C" void kernel_launch(void* const* d_in, const int* in_sizes, int n_in,
                              void* d_out, int out_size) {
    const float* x    = (const float*)d_in[0];
    const float* wgt  = (const float*)d_in[1];
    const float* bias = (const float*)d_in[2];
    float* out = (float*)d_out;

    __half *a1, *a2, *a3, *wh;
    float *y1, *y2, *y3;
    cudaGetSymbolAddress((void**)&a1, g_a1);
    cudaGetSymbolAddress((void**)&a2, g_a2);
    cudaGetSymbolAddress((void**)&a3, g_a3);
    cudaGetSymbolAddress((void**)&wh, g_w);
    cudaGetSymbolAddress((void**)&y1, g_y1);
    cudaGetSymbolAddress((void**)&y2, g_y2);
    cudaGetSymbolAddress((void**)&y3, g_y3);

    cudaFuncSetAttribute(conv_mma, cudaFuncAttributeMaxDynamicSharedMemorySize, SMEM_TOTAL);

    // 0: full DWT cascade + weight convert
    dwtall_k<<<WCONV_BLKS + CASC_BLKS, 256>>>(x, wgt, wh, a1, a2, a3);
    // 1: all convs
    conv_mma<<<NT1 + NT2 + NT3, 256, SMEM_TOTAL>>>(a1, y1, a2, y2, a3, y3, wh);
    // 2: full IDWT cascade + bias + NCHW output
    idwtall_k<<<CASC_BLKS, 256>>>(y1, y2, y3, out, bias);
}